// round 2
// baseline (speedup 1.0000x reference)
#include <cuda_runtime.h>

// Problem constants
constexpr int B  = 2;
constexpr int S  = 2048;
constexpr int D  = 512;
constexpr int H  = 8;
constexpr int DK = 64;           // D / H

// Scratch (allocation-free rule: __device__ globals)
__device__ float g_Q[B * H * S * DK];   // [B,H,S,DK]
__device__ float g_K[B * H * S * DK];
__device__ float g_V[B * H * S * DK];
__device__ float g_X[B * S * D];        // attention output, [B,S,D]

// ---------------------------------------------------------------------------
// GEMM: out[m,n] = sum_k A[m,k] * W[n,k]   (A: [4096,512], W: [512,512])
// 64x64 tile, BK=32, 256 threads, 4x4 frags. SPLIT writes head-split layout.
// ---------------------------------------------------------------------------

__global__ __launch_bounds__(256) void proj_qkv_kernel(
    const float* __restrict__ qin, const float* __restrict__ kin,
    const float* __restrict__ vin, const float* __restrict__ W)
{
    const float* A;
    float* out;
    if (blockIdx.z == 0)      { A = qin; out = g_Q; }
    else if (blockIdx.z == 1) { A = kin; out = g_K; }
    else                      { A = vin; out = g_V; }

    __shared__ float As[32][68];   // [k][m]
    __shared__ float Bs[32][68];   // [k][n]

    const int tid = threadIdx.x;
    const int ty = tid >> 4;       // 0..15  -> rows ty*4..+3
    const int tx = tid & 15;       // 0..15  -> cols tx*4..+3
    const int m0 = blockIdx.y * 64;
    const int n0 = blockIdx.x * 64;

    float acc[4][4] = {};

    for (int kt = 0; kt < D; kt += 32) {
        // load tiles (transposed into smem)
        #pragma unroll
        for (int q2 = 0; q2 < 2; q2++) {
            int id = tid * 2 + q2;       // 0..511
            int m  = id >> 3;            // 0..63
            int kq = (id & 7) * 4;       // 0..28
            float4 fa = *(const float4*)&A[(m0 + m) * D + kt + kq];
            As[kq + 0][m] = fa.x; As[kq + 1][m] = fa.y;
            As[kq + 2][m] = fa.z; As[kq + 3][m] = fa.w;
            float4 fb = *(const float4*)&W[(n0 + m) * D + kt + kq];
            Bs[kq + 0][m] = fb.x; Bs[kq + 1][m] = fb.y;
            Bs[kq + 2][m] = fb.z; Bs[kq + 3][m] = fb.w;
        }
        __syncthreads();

        #pragma unroll 8
        for (int kk = 0; kk < 32; kk++) {
            float4 af = *(const float4*)&As[kk][ty * 4];
            float4 bf = *(const float4*)&Bs[kk][tx * 4];
            float av[4] = {af.x, af.y, af.z, af.w};
            float bv[4] = {bf.x, bf.y, bf.z, bf.w};
            #pragma unroll
            for (int i = 0; i < 4; i++)
                #pragma unroll
                for (int j = 0; j < 4; j++)
                    acc[i][j] = fmaf(av[i], bv[j], acc[i][j]);
        }
        __syncthreads();
    }

    // write head-split: out[((b*H + h)*S + s)*DK + dk]
    const int h = n0 >> 6;           // n0 multiple of 64 -> fixed head
    #pragma unroll
    for (int i = 0; i < 4; i++) {
        int m = m0 + ty * 4 + i;
        int b = m >> 11;             // m / 2048
        int s = m & 2047;
        float4 r = make_float4(acc[i][0], acc[i][1], acc[i][2], acc[i][3]);
        *(float4*)&out[(((b * H + h) * S) + s) * DK + tx * 4] = r;
    }
}

__global__ __launch_bounds__(256) void proj_out_kernel(
    const float* __restrict__ W, float* __restrict__ out)
{
    __shared__ float As[32][68];
    __shared__ float Bs[32][68];

    const int tid = threadIdx.x;
    const int ty = tid >> 4;
    const int tx = tid & 15;
    const int m0 = blockIdx.y * 64;
    const int n0 = blockIdx.x * 64;

    float acc[4][4] = {};

    for (int kt = 0; kt < D; kt += 32) {
        #pragma unroll
        for (int q2 = 0; q2 < 2; q2++) {
            int id = tid * 2 + q2;
            int m  = id >> 3;
            int kq = (id & 7) * 4;
            float4 fa = *(const float4*)&g_X[(m0 + m) * D + kt + kq];
            As[kq + 0][m] = fa.x; As[kq + 1][m] = fa.y;
            As[kq + 2][m] = fa.z; As[kq + 3][m] = fa.w;
            float4 fb = *(const float4*)&W[(n0 + m) * D + kt + kq];
            Bs[kq + 0][m] = fb.x; Bs[kq + 1][m] = fb.y;
            Bs[kq + 2][m] = fb.z; Bs[kq + 3][m] = fb.w;
        }
        __syncthreads();

        #pragma unroll 8
        for (int kk = 0; kk < 32; kk++) {
            float4 af = *(const float4*)&As[kk][ty * 4];
            float4 bf = *(const float4*)&Bs[kk][tx * 4];
            float av[4] = {af.x, af.y, af.z, af.w};
            float bv[4] = {bf.x, bf.y, bf.z, bf.w};
            #pragma unroll
            for (int i = 0; i < 4; i++)
                #pragma unroll
                for (int j = 0; j < 4; j++)
                    acc[i][j] = fmaf(av[i], bv[j], acc[i][j]);
        }
        __syncthreads();
    }

    #pragma unroll
    for (int i = 0; i < 4; i++) {
        int m = m0 + ty * 4 + i;
        float4 r = make_float4(acc[i][0], acc[i][1], acc[i][2], acc[i][3]);
        *(float4*)&out[m * D + n0 + tx * 4] = r;
    }
}

// ---------------------------------------------------------------------------
// Attention: per (b,h) and 64-row q-tile, stream 64-wide K/V tiles with
// online softmax. mask==0 -> score := 1e-9 (pre-softmax, NOT -inf).
// ---------------------------------------------------------------------------

__global__ __launch_bounds__(256, 2) void attn_kernel(const int* __restrict__ mask)
{
    const int q0 = blockIdx.x * 64;
    const int bh = blockIdx.y;                 // b*H + h
    const float* Qp = g_Q + (size_t)bh * S * DK;
    const float* Kp = g_K + (size_t)bh * S * DK;
    const float* Vp = g_V + (size_t)bh * S * DK;

    __shared__ float Qst[64][68];  // [d][r]
    __shared__ float Kst[64][68];  // [d][c]
    __shared__ float Vs [64][68];  // [k][dv]
    __shared__ float Ps [64][68];  // [r][c]

    const int tid = threadIdx.x;
    const int ty = tid >> 4;       // rows ty*4..+3
    const int tx = tid & 15;       // cols tx*4..+3
    const int ty4 = ty * 4, tx4 = tx * 4;

    // load Q tile transposed
    {
        int r  = tid >> 2;
        int dq = (tid & 3) * 16;
        #pragma unroll
        for (int l = 0; l < 4; l++) {
            float4 f = *(const float4*)&Qp[(q0 + r) * DK + dq + l * 4];
            Qst[dq + l * 4 + 0][r] = f.x; Qst[dq + l * 4 + 1][r] = f.y;
            Qst[dq + l * 4 + 2][r] = f.z; Qst[dq + l * 4 + 3][r] = f.w;
        }
    }

    float o[4][4] = {};
    float rmax[4], rsum[4];
    #pragma unroll
    for (int i = 0; i < 4; i++) { rmax[i] = -1e30f; rsum[i] = 0.f; }

    for (int k0 = 0; k0 < S; k0 += 64) {
        __syncthreads();   // prior-iteration consumers done (also covers Q load)
        {
            int r  = tid >> 2;
            int dq = (tid & 3) * 16;
            #pragma unroll
            for (int l = 0; l < 4; l++) {
                float4 f = *(const float4*)&Kp[(k0 + r) * DK + dq + l * 4];
                Kst[dq + l * 4 + 0][r] = f.x; Kst[dq + l * 4 + 1][r] = f.y;
                Kst[dq + l * 4 + 2][r] = f.z; Kst[dq + l * 4 + 3][r] = f.w;
                float4 g = *(const float4*)&Vp[(k0 + r) * DK + dq + l * 4];
                *(float4*)&Vs[r][dq + l * 4] = g;
            }
        }
        __syncthreads();

        // scores tile: acc[i][j] = Q[r,:] . K[c,:]
        float acc[4][4] = {};
        #pragma unroll 16
        for (int d = 0; d < 64; d++) {
            float4 af = *(const float4*)&Qst[d][ty4];
            float4 bf = *(const float4*)&Kst[d][tx4];
            float av[4] = {af.x, af.y, af.z, af.w};
            float bv[4] = {bf.x, bf.y, bf.z, bf.w};
            #pragma unroll
            for (int i = 0; i < 4; i++)
                #pragma unroll
                for (int j = 0; j < 4; j++)
                    acc[i][j] = fmaf(av[i], bv[j], acc[i][j]);
        }

        // scale + mask + online softmax (per local row i; 16 lanes own a row)
        #pragma unroll
        for (int i = 0; i < 4; i++) {
            int gq = q0 + ty4 + i;
            int4 mr = *(const int4*)&mask[(size_t)gq * S + k0 + tx4];
            float sc[4];
            sc[0] = (mr.x == 0) ? 1e-9f : acc[i][0] * 0.125f;
            sc[1] = (mr.y == 0) ? 1e-9f : acc[i][1] * 0.125f;
            sc[2] = (mr.z == 0) ? 1e-9f : acc[i][2] * 0.125f;
            sc[3] = (mr.w == 0) ? 1e-9f : acc[i][3] * 0.125f;

            float tmax = fmaxf(fmaxf(sc[0], sc[1]), fmaxf(sc[2], sc[3]));
            #pragma unroll
            for (int off = 8; off > 0; off >>= 1)
                tmax = fmaxf(tmax, __shfl_xor_sync(0xffffffffu, tmax, off));

            float nm   = fmaxf(rmax[i], tmax);
            float corr = __expf(rmax[i] - nm);
            rmax[i] = nm;

            float p0 = __expf(sc[0] - nm);
            float p1 = __expf(sc[1] - nm);
            float p2 = __expf(sc[2] - nm);
            float p3 = __expf(sc[3] - nm);
            float ts = (p0 + p1) + (p2 + p3);
            #pragma unroll
            for (int off = 8; off > 0; off >>= 1)
                ts += __shfl_xor_sync(0xffffffffu, ts, off);

            rsum[i] = rsum[i] * corr + ts;
            #pragma unroll
            for (int j = 0; j < 4; j++) o[i][j] *= corr;

            *(float4*)&Ps[ty4 + i][tx4] = make_float4(p0, p1, p2, p3);
        }
        __syncthreads();

        // O += P * V
        #pragma unroll 16
        for (int kk = 0; kk < 64; kk++) {
            float4 bf = *(const float4*)&Vs[kk][tx4];
            float bv[4] = {bf.x, bf.y, bf.z, bf.w};
            float av[4];
            #pragma unroll
            for (int i = 0; i < 4; i++) av[i] = Ps[ty4 + i][kk];
            #pragma unroll
            for (int i = 0; i < 4; i++)
                #pragma unroll
                for (int j = 0; j < 4; j++)
                    o[i][j] = fmaf(av[i], bv[j], o[i][j]);
        }
    }

    // normalize and write back to [B,S,D]
    const int b = bh >> 3;
    const int h = bh & 7;
    #pragma unroll
    for (int i = 0; i < 4; i++) {
        float inv = 1.f / rsum[i];
        int s = q0 + ty4 + i;
        float4 r = make_float4(o[i][0] * inv, o[i][1] * inv,
                               o[i][2] * inv, o[i][3] * inv);
        *(float4*)&g_X[((size_t)b * S + s) * D + h * DK + tx4] = r;
    }
}

// ---------------------------------------------------------------------------

extern "C" void kernel_launch(void* const* d_in, const int* in_sizes, int n_in,
                              void* d_out, int out_size)
{
    const float* q    = (const float*)d_in[0];
    const float* k    = (const float*)d_in[1];
    const float* v    = (const float*)d_in[2];
    const int*   mask = (const int*)d_in[3];
    const float* Wq   = (const float*)d_in[4];
    const float* Wo   = (const float*)d_in[5];
    float* out = (float*)d_out;

    proj_qkv_kernel<<<dim3(D / 64, (B * S) / 64, 3), 256>>>(q, k, v, Wq);
    attn_kernel<<<dim3(S / 64, B * H), 256>>>(mask);
    proj_out_kernel<<<dim3(D / 64, (B * S) / 64), 256>>>(Wo, out);
}